// round 8
// baseline (speedup 1.0000x reference)
#include <cuda_runtime.h>
#include <cuda_bf16.h>
#include <cstdint>

// Problem constants
#define BATCH   2
#define SEQ     2048
#define DMODEL  1024
#define NHEAD   16
#define HDIM    64
#define MTOT    (BATCH * SEQ)   // 4096

// Scratch (device globals — no allocation allowed)
__device__ float g_q[BATCH * NHEAD * SEQ * HDIM];  // [b,h,s,d]
__device__ float g_k[BATCH * NHEAD * SEQ * HDIM];
__device__ float g_v[BATCH * NHEAD * SEQ * HDIM];
__device__ float g_y[MTOT * DMODEL];               // attention output, [b*s, d]

// ============================================================================
// Baseline-PTX tensor-core helpers (valid on plain sm_103 target)
// ============================================================================
__device__ __forceinline__ uint32_t smem_to_u32(const void* p) {
    uint32_t a;
    asm("{ .reg .u64 t; cvta.to.shared.u64 t, %1; cvt.u32.u64 %0, t; }" : "=r"(a) : "l"(p));
    return a;
}

__device__ __forceinline__ void ldsm_x4(uint32_t* r, uint32_t addr) {
    asm volatile("ldmatrix.sync.aligned.m8n8.x4.shared.b16 {%0,%1,%2,%3}, [%4];"
        : "=r"(r[0]), "=r"(r[1]), "=r"(r[2]), "=r"(r[3]) : "r"(addr));
}

__device__ __forceinline__ void mma16816(float* d, const uint32_t* a, const uint32_t* b) {
    asm volatile(
        "mma.sync.aligned.m16n8k16.row.col.f32.bf16.bf16.f32 "
        "{%0,%1,%2,%3}, {%4,%5,%6,%7}, {%8,%9}, {%0,%1,%2,%3};"
        : "+f"(d[0]), "+f"(d[1]), "+f"(d[2]), "+f"(d[3])
        : "r"(a[0]), "r"(a[1]), "r"(a[2]), "r"(a[3]), "r"(b[0]), "r"(b[1]));
}

// fp32 x8 -> bf16 hi/lo split, packed, stored 16B each to smem
__device__ __forceinline__ void cvt_store(const float4 v0, const float4 v1, char* hp, char* lp) {
    float f[8] = {v0.x, v0.y, v0.z, v0.w, v1.x, v1.y, v1.z, v1.w};
    uint32_t hw[4], lw[4];
    #pragma unroll
    for (int i = 0; i < 4; i++) {
        float a = f[2 * i], b = f[2 * i + 1];
        uint32_t hp2;
        asm("cvt.rn.bf16x2.f32 %0, %1, %2;" : "=r"(hp2) : "f"(b), "f"(a));  // low=a, high=b
        float ha = __uint_as_float(hp2 << 16);
        float hb = __uint_as_float(hp2 & 0xFFFF0000u);
        float ra = a - ha, rb = b - hb;
        uint32_t lp2;
        asm("cvt.rn.bf16x2.f32 %0, %1, %2;" : "=r"(lp2) : "f"(rb), "f"(ra));
        hw[i] = hp2; lw[i] = lp2;
    }
    *(uint4*)hp = make_uint4(hw[0], hw[1], hw[2], hw[3]);
    *(uint4*)lp = make_uint4(lw[0], lw[1], lw[2], lw[3]);
}

// ============================================================================
// mma.sync GEMM: C[m,n] = A[m,k] . W[n,k]  (A @ W^T), fp32 in/out, bf16-split.
// 128x128 CTA tile, 512 threads = 16 warps (2m x 8n), warp tile 64x16.
// K-chunks of 32, double-buffered smem. Smem halves: AH, AL, BH, BL; each
// 128 rows x padded-stride 40 bf16 (80 B) -> conflict-free LDSM.
// MODE 0: A=x, W per blockIdx.z {wq,wk,wv}, scatter into g_q/g_k/g_v [b,h,s,d]
// MODE 1: A=g_y, W=wo, out = C + bias
// ============================================================================
#define KCHUNK   32
#define NKC      (DMODEL / KCHUNK)   // 32
#define SROW_B   80                   // bytes per smem row (40 bf16)
#define HALF_B   (128 * SROW_B)       // 10240 B per matrix-half
#define STAGE_B  (4 * HALF_B)         // AH, AL, BH, BL = 40960 B
#define GEMM_SMEM (2 * STAGE_B)       // 81920 B

template <int MODE>
__global__ __launch_bounds__(512)
void gemm_mma(const float* __restrict__ Ain,
              const float* __restrict__ W0,
              const float* __restrict__ W1,
              const float* __restrict__ W2,
              const float* __restrict__ bias,
              float* __restrict__ Out)
{
    extern __shared__ char smem[];
    const uint32_t smem_u = smem_to_u32(smem);

    const int tid  = threadIdx.x;
    const int lane = tid & 31;
    const int wid  = tid >> 5;
    const int wm   = wid >> 3;      // 0..1 -> 64-row band
    const int wn   = wid & 7;       // 0..7 -> 16-col band
    const int m0 = blockIdx.y * 128;
    const int n0 = blockIdx.x * 128;

    const float* A = (MODE == 0) ? Ain : g_y;
    const float* W;
    if (MODE == 0) {
        const int z = blockIdx.z;
        W = (z == 0) ? W0 : ((z == 1) ? W1 : W2);
    } else {
        W = W0;
    }

    // Loader mapping: one 8-float unit per thread: row = tid>>2, cols (tid&3)*8..+7
    const int lrow = tid >> 2;              // 0..127
    const int lc0  = (tid & 3) * 8;         // 0,8,16,24
    const float* ag = A + (size_t)(m0 + lrow) * DMODEL + lc0;
    const float* bg = W + (size_t)(n0 + lrow) * DMODEL + lc0;
    const uint32_t sto = lrow * SROW_B + lc0 * 2;   // byte offset inside a half

    // ldmatrix per-lane byte offsets (within a half, before k-step offset)
    // A x4 (one m16 tile, k0..k15): lanes 0-15 rows, lane>>4 selects k half
    const uint32_t a_byte = (uint32_t)(wm * 64 + (lane & 15)) * SROW_B + (lane >> 4) * 16;
    // B x4 (two n8 tiles stacked, k0..k15): mats = {n0 k0, n0 k8, n+8 k0, n+8 k8}
    const uint32_t b_row  = wn * 16 + (lane & 7) + ((lane >> 4) << 3);
    const uint32_t b_byte = b_row * SROW_B + ((lane >> 3) & 1) * 16;

    float acc[4][2][4];
    #pragma unroll
    for (int mt = 0; mt < 4; mt++)
        #pragma unroll
        for (int nt = 0; nt < 2; nt++)
            #pragma unroll
            for (int e = 0; e < 4; e++) acc[mt][nt][e] = 0.0f;

    auto store_stage = [&](int s, float4 a0, float4 a1, float4 b0, float4 b1) {
        char* base = smem + s * STAGE_B;
        cvt_store(a0, a1, base + sto, base + HALF_B + sto);
        cvt_store(b0, b1, base + 2 * HALF_B + sto, base + 3 * HALF_B + sto);
    };

    // Prefill chunk 0
    {
        float4 a0 = *(const float4*)(ag);
        float4 a1 = *(const float4*)(ag + 4);
        float4 b0 = *(const float4*)(bg);
        float4 b1 = *(const float4*)(bg + 4);
        store_stage(0, a0, a1, b0, b1);
    }
    __syncthreads();

    for (int kc = 0; kc < NKC; kc++) {
        const int s = kc & 1;
        float4 pa0, pa1, pb0, pb1;
        if (kc + 1 < NKC) {
            const float* a = ag + (kc + 1) * KCHUNK;
            const float* b = bg + (kc + 1) * KCHUNK;
            pa0 = *(const float4*)(a);
            pa1 = *(const float4*)(a + 4);
            pb0 = *(const float4*)(b);
            pb1 = *(const float4*)(b + 4);
        }

        const uint32_t sb = smem_u + s * STAGE_B;
        #pragma unroll
        for (int ks = 0; ks < 2; ks++) {
            const uint32_t kb = ks * 32;    // 16 bf16 = 32 B per k-step
            uint32_t aH[4][4], aL[4][4], bH[4], bL[4];
            #pragma unroll
            for (int mt = 0; mt < 4; mt++) {
                ldsm_x4(aH[mt], sb + a_byte + kb + mt * 16 * SROW_B);
                ldsm_x4(aL[mt], sb + HALF_B + a_byte + kb + mt * 16 * SROW_B);
            }
            ldsm_x4(bH, sb + 2 * HALF_B + b_byte + kb);
            ldsm_x4(bL, sb + 3 * HALF_B + b_byte + kb);

            #pragma unroll
            for (int mt = 0; mt < 4; mt++)
                #pragma unroll
                for (int nt = 0; nt < 2; nt++) {
                    mma16816(acc[mt][nt], aH[mt], bH + nt * 2);
                    mma16816(acc[mt][nt], aH[mt], bL + nt * 2);
                    mma16816(acc[mt][nt], aL[mt], bH + nt * 2);
                }
        }
        __syncthreads();
        if (kc + 1 < NKC) {
            store_stage(s ^ 1, pa0, pa1, pb0, pb1);
            __syncthreads();
        }
    }

    // Epilogue. D fragment: d0,d1 -> (row lane>>2, col 2*(lane&3)+{0,1}),
    // d2,d3 -> row+8.
    #pragma unroll
    for (int mt = 0; mt < 4; mt++) {
        const int row0 = m0 + wm * 64 + mt * 16 + (lane >> 2);
        #pragma unroll
        for (int nt = 0; nt < 2; nt++) {
            const int col = n0 + wn * 16 + nt * 8 + 2 * (lane & 3);
            const float* a = acc[mt][nt];
            if (MODE == 0) {
                const int z = blockIdx.z;
                float* dst = (z == 0) ? g_q : ((z == 1) ? g_k : g_v);
                const int h = col >> 6;
                const int d = col & (HDIM - 1);
                #pragma unroll
                for (int rh = 0; rh < 2; rh++) {
                    const int m = row0 + rh * 8;
                    const int b = m >> 11;
                    const int sq = m & (SEQ - 1);
                    *(float2*)&dst[(((size_t)(b * NHEAD + h) * SEQ) + sq) * HDIM + d] =
                        make_float2(a[rh * 2], a[rh * 2 + 1]);
                }
            } else {
                const float b0 = bias[col], b1 = bias[col + 1];
                *(float2*)&Out[(size_t)row0 * DMODEL + col] = make_float2(a[0] + b0, a[1] + b1);
                *(float2*)&Out[(size_t)(row0 + 8) * DMODEL + col] = make_float2(a[2] + b0, a[3] + b1);
            }
        }
    }
}

// ----------------------------------------------------------------------------
// Flash attention (unchanged SIMT): one block = 64 queries of one (b,h).
// ----------------------------------------------------------------------------
__global__ __launch_bounds__(256)
void attn_kernel()
{
    extern __shared__ float sm[];
    float* Qs = sm;                  // [64][65]
    float* KP = sm + 64 * 65;        // [64][65]
    float* Vs = sm + 2 * 64 * 65;    // [64][64]

    const int qt = blockIdx.x;
    const int bh = blockIdx.y;
    const float* qp = g_q + ((size_t)bh * SEQ + qt * 64) * HDIM;
    const float* kp = g_k + (size_t)bh * SEQ * HDIM;
    const float* vp = g_v + (size_t)bh * SEQ * HDIM;

    const int tid = threadIdx.x;
    const int tx = tid & 15;
    const int ty = tid >> 4;
    const float scale = 0.125f;

    for (int f = tid; f < 1024; f += 256) {
        const int row = f >> 4;
        const int c4  = (f & 15) * 4;
        float4 v = *(const float4*)&qp[row * HDIM + c4];
        float* d = &Qs[row * 65 + c4];
        d[0] = v.x * scale; d[1] = v.y * scale; d[2] = v.z * scale; d[3] = v.w * scale;
    }

    float mx[4], ls[4], o[4][4];
    #pragma unroll
    for (int i = 0; i < 4; i++) {
        mx[i] = -1e30f; ls[i] = 0.0f;
        #pragma unroll
        for (int j = 0; j < 4; j++) o[i][j] = 0.0f;
    }

    for (int t = 0; t < SEQ / 64; t++) {
        __syncthreads();
        for (int f = tid; f < 1024; f += 256) {
            const int row = f >> 4;
            const int c4  = (f & 15) * 4;
            float4 kv = *(const float4*)&kp[((size_t)t * 64 + row) * HDIM + c4];
            float* dk = &KP[row * 65 + c4];
            dk[0] = kv.x; dk[1] = kv.y; dk[2] = kv.z; dk[3] = kv.w;
            float4 vv = *(const float4*)&vp[((size_t)t * 64 + row) * HDIM + c4];
            float* dv = &Vs[row * 64 + c4];
            dv[0] = vv.x; dv[1] = vv.y; dv[2] = vv.z; dv[3] = vv.w;
        }
        __syncthreads();

        float s[4][4];
        #pragma unroll
        for (int i = 0; i < 4; i++)
            #pragma unroll
            for (int j = 0; j < 4; j++) s[i][j] = 0.0f;

        #pragma unroll 8
        for (int kk = 0; kk < 64; kk++) {
            float a[4], b[4];
            #pragma unroll
            for (int i = 0; i < 4; i++) a[i] = Qs[(4 * ty + i) * 65 + kk];
            #pragma unroll
            for (int j = 0; j < 4; j++) b[j] = KP[(4 * tx + j) * 65 + kk];
            #pragma unroll
            for (int i = 0; i < 4; i++)
                #pragma unroll
                for (int j = 0; j < 4; j++)
                    s[i][j] += a[i] * b[j];
        }

        #pragma unroll
        for (int i = 0; i < 4; i++) {
            float tm = fmaxf(fmaxf(s[i][0], s[i][1]), fmaxf(s[i][2], s[i][3]));
            #pragma unroll
            for (int off = 8; off > 0; off >>= 1)
                tm = fmaxf(tm, __shfl_xor_sync(0xffffffffu, tm, off));
            const float nm = fmaxf(mx[i], tm);
            const float corr = __expf(mx[i] - nm);
            float r = 0.0f;
            #pragma unroll
            for (int j = 0; j < 4; j++) {
                s[i][j] = __expf(s[i][j] - nm);
                r += s[i][j];
            }
            #pragma unroll
            for (int off = 8; off > 0; off >>= 1)
                r += __shfl_xor_sync(0xffffffffu, r, off);
            ls[i] = ls[i] * corr + r;
            mx[i] = nm;
            #pragma unroll
            for (int j = 0; j < 4; j++) o[i][j] *= corr;
        }

        __syncthreads();
        #pragma unroll
        for (int i = 0; i < 4; i++)
            #pragma unroll
            for (int j = 0; j < 4; j++)
                KP[(4 * ty + i) * 65 + 4 * tx + j] = s[i][j];
        __syncthreads();

        #pragma unroll 8
        for (int ss = 0; ss < 64; ss++) {
            float a[4], b[4];
            #pragma unroll
            for (int i = 0; i < 4; i++) a[i] = KP[(4 * ty + i) * 65 + ss];
            #pragma unroll
            for (int j = 0; j < 4; j++) b[j] = Vs[ss * 64 + 4 * tx + j];
            #pragma unroll
            for (int i = 0; i < 4; i++)
                #pragma unroll
                for (int j = 0; j < 4; j++)
                    o[i][j] += a[i] * b[j];
        }
    }

    const int b = bh / NHEAD;
    const int h = bh % NHEAD;
    #pragma unroll
    for (int i = 0; i < 4; i++) {
        const float inv = 1.0f / ls[i];
        const int srow = qt * 64 + 4 * ty + i;
        float4 v = make_float4(o[i][0] * inv, o[i][1] * inv, o[i][2] * inv, o[i][3] * inv);
        *(float4*)&g_y[((size_t)(b * SEQ + srow)) * DMODEL + h * HDIM + 4 * tx] = v;
    }
}

// ----------------------------------------------------------------------------
// Launch
// ----------------------------------------------------------------------------
extern "C" void kernel_launch(void* const* d_in, const int* in_sizes, int n_in,
                              void* d_out, int out_size)
{
    const float* x  = (const float*)d_in[0];
    const float* wq = (const float*)d_in[1];
    const float* wk = (const float*)d_in[2];
    const float* wv = (const float*)d_in[3];
    const float* wo = (const float*)d_in[4];
    const float* bo = (const float*)d_in[5];
    float* out = (float*)d_out;

    cudaFuncSetAttribute(gemm_mma<0>, cudaFuncAttributeMaxDynamicSharedMemorySize, GEMM_SMEM);
    cudaFuncSetAttribute(gemm_mma<1>, cudaFuncAttributeMaxDynamicSharedMemorySize, GEMM_SMEM);

    // 1) Fused QKV projection on tensor cores (bf16-split, fp32-accurate)
    gemm_mma<0><<<dim3(DMODEL / 128, MTOT / 128, 3), 512, GEMM_SMEM>>>(x, wq, wk, wv, nullptr, nullptr);

    // 2) Flash attention (SIMT, unchanged)
    const size_t smem = (size_t)(2 * 64 * 65 + 64 * 64) * sizeof(float);
    cudaFuncSetAttribute(attn_kernel, cudaFuncAttributeMaxDynamicSharedMemorySize, (int)smem);
    attn_kernel<<<dim3(SEQ / 64, BATCH * NHEAD), 256, smem>>>();

    // 3) Output projection + bias on tensor cores
    gemm_mma<1><<<dim3(DMODEL / 128, MTOT / 128, 1), 512, GEMM_SMEM>>>(nullptr, wo, nullptr, nullptr, bo, out);
}